// round 5
// baseline (speedup 1.0000x reference)
#include <cuda_runtime.h>

#define HID 10
#define ROWF 2048                 // floats per row
#define WARPS 8
#define THREADS 256

typedef unsigned long long ull;

__device__ __forceinline__ void fma2(ull& acc, ull a, ull b) {
    asm("fma.rn.f32x2 %0, %1, %2, %0;" : "+l"(acc) : "l"(a), "l"(b));
}
__device__ __forceinline__ float2 unp(ull v) {
    float2 r; asm("mov.b64 {%0,%1}, %2;" : "=f"(r.x), "=f"(r.y) : "l"(v)); return r;
}
__device__ __forceinline__ ull pk(float lo, float hi) {
    ull v; asm("mov.b64 %0, {%1,%2};" : "=l"(v) : "f"(lo), "f"(hi)); return v;
}

// aQ[t2*20 + sub*10 + j] = f32x2( W1[32+4t2+2sub][j], W1[33+4t2+2sub][j] )
// bQ[q*22 + sub*10 + j]  = f32x2( W1[4q+2sub][j],     W1[4q+2sub+1][j] )   (stride 22 kills bank conflicts)
__global__ __launch_bounds__(THREADS, 2)
void iin_kernel(const float* __restrict__ outputs,
                const int* __restrict__ tests32,
                const long long* __restrict__ tests64,
                const float* __restrict__ W1,
                const float* __restrict__ b1,
                const float* __restrict__ W2,
                float* __restrict__ out,
                int B)
{
    __shared__ ull aQ[160];
    __shared__ ull bQ[176];
    __shared__ float epi[20];     // w2[0..9], b1[10..19]

    const int tid  = threadIdx.x;
    const int lane = tid & 31;
    const int warp = tid >> 5;

    for (int idx = tid; idx < 160; idx += THREADS) {
        int t2 = idx / 20, r = idx % 20, sub = r / 10, j = r % 10;
        int d0 = 32 + 4 * t2 + 2 * sub;
        aQ[t2 * 20 + sub * 10 + j] = pk(W1[d0 * HID + j], W1[(d0 + 1) * HID + j]);
        int e0 = 4 * t2 + 2 * sub;
        bQ[t2 * 22 + sub * 10 + j] = pk(W1[e0 * HID + j], W1[(e0 + 1) * HID + j]);
    }
    if (tid < 10) { epi[tid] = W2[tid]; epi[tid + 10] = b1[tid]; }
    __syncthreads();

    // tests dtype probe: int64 -> every odd int32 word is a zero high-half
    int pidx = 2 * lane + 1; if (pidx > 2 * B - 1) pidx = 2 * B - 1;
    const bool idx32 = __any_sync(0xffffffffu, tests32[pidx] != 0);

    const unsigned q = lane & 7;
    const double2* bp2 = (const double2*)(bQ + q * 22);

    const int gw      = blockIdx.x * WARPS + warp;
    const int gstride = gridDim.x * WARPS;

    for (int row = gw; row < B; row += gstride) {
        // person / location first (their loads are covered by the main loop)
        int person, loc;
        if (idx32) { person = tests32[2 * row];      loc = tests32[2 * row + 1]; }
        else       { person = (int)tests64[2 * row]; loc = (int)tests64[2 * row + 1]; }

        const float4* grow = (const float4*)outputs + (size_t)row * 512;
        float4 pv = grow[(unsigned)person * 8 + q];          // person vec: one 128B line

        // wire0 = lane : chunks grow[lane*8 + k]; wire1 = lane+32 : grow[256 + lane*8 + k]
        const float4* g0 = grow + lane * 8;
        float4 d[8];
#pragma unroll
        for (int k = 0; k < 8; ++k) d[k] = g0[k];

        ull acc0[HID], acc1[HID];
#pragma unroll
        for (int j = 0; j < HID; ++j) acc0[j] = 0ULL;

#pragma unroll
        for (int t2 = 0; t2 < 8; ++t2) {
            ull x01 = pk(d[t2].x, d[t2].y);
            ull x23 = pk(d[t2].z, d[t2].w);
            d[t2] = g0[256 + t2];                            // prefetch wire1 chunk into freed slot
            const double2* ap = (const double2*)(aQ + t2 * 20);
#pragma unroll
            for (int jj = 0; jj < 5; ++jj) {
                double2 A0 = ap[jj], A1 = ap[jj + 5];
                fma2(acc0[2 * jj],     x01, __double_as_longlong(A0.x));
                fma2(acc0[2 * jj + 1], x01, __double_as_longlong(A0.y));
                fma2(acc0[2 * jj],     x23, __double_as_longlong(A1.x));
                fma2(acc0[2 * jj + 1], x23, __double_as_longlong(A1.y));
            }
        }

#pragma unroll
        for (int j = 0; j < HID; ++j) acc1[j] = 0ULL;
#pragma unroll
        for (int t2 = 0; t2 < 8; ++t2) {
            ull x01 = pk(d[t2].x, d[t2].y);
            ull x23 = pk(d[t2].z, d[t2].w);
            const double2* ap = (const double2*)(aQ + t2 * 20);
#pragma unroll
            for (int jj = 0; jj < 5; ++jj) {
                double2 A0 = ap[jj], A1 = ap[jj + 5];
                fma2(acc1[2 * jj],     x01, __double_as_longlong(A0.x));
                fma2(acc1[2 * jj + 1], x01, __double_as_longlong(A0.y));
                fma2(acc1[2 * jj],     x23, __double_as_longlong(A1.x));
                fma2(acc1[2 * jj + 1], x23, __double_as_longlong(A1.y));
            }
        }

        // person partial: 8-lane groups, group member q handles d = 4q..4q+3
        ull xp01 = pk(pv.x, pv.y), xp23 = pk(pv.z, pv.w);
        ull s2[HID];
#pragma unroll
        for (int j = 0; j < HID; ++j) s2[j] = 0ULL;
#pragma unroll
        for (int jj = 0; jj < 5; ++jj) {
            double2 B0 = bp2[jj], B1 = bp2[jj + 5];
            fma2(s2[2 * jj],     xp01, __double_as_longlong(B0.x));
            fma2(s2[2 * jj + 1], xp01, __double_as_longlong(B0.y));
            fma2(s2[2 * jj],     xp23, __double_as_longlong(B1.x));
            fma2(s2[2 * jj + 1], xp23, __double_as_longlong(B1.y));
        }
        float pb[HID];
#pragma unroll
        for (int j = 0; j < HID; ++j) { float2 f = unp(s2[j]); pb[j] = f.x + f.y; }
#pragma unroll
        for (int off = 4; off; off >>= 1)
#pragma unroll
            for (int j = 0; j < HID; ++j)
                pb[j] += __shfl_xor_sync(0xffffffffu, pb[j], off);

        // logits (b2 cancels in lse - logit)
        float lg0 = 0.f, lg1 = 0.f;
#pragma unroll
        for (int j = 0; j < HID; ++j) {
            float bj = pb[j] + epi[10 + j];
            float2 f0 = unp(acc0[j]), f1 = unp(acc1[j]);
            float q0 = fmaxf(f0.x + f0.y + bj, 0.f);
            float q1 = fmaxf(f1.x + f1.y + bj, 0.f);
            lg0 = fmaf(q0, epi[j], lg0);
            lg1 = fmaf(q1, epi[j], lg1);
        }

        // log-softmax over 64 wires
        float m = fmaxf(lg0, lg1);
#pragma unroll
        for (int off = 16; off; off >>= 1)
            m = fmaxf(m, __shfl_xor_sync(0xffffffffu, m, off));
        float s = __expf(lg0 - m) + __expf(lg1 - m);
#pragma unroll
        for (int off = 16; off; off >>= 1)
            s += __shfl_xor_sync(0xffffffffu, s, off);
        float lse = m + __logf(s);

        float sel = (loc >= 32) ? lg1 : lg0;
        float lv  = __shfl_sync(0xffffffffu, sel, loc & 31);
        if (lane == 0) out[row] = lse - lv;
    }
}

extern "C" void kernel_launch(void* const* d_in, const int* in_sizes, int n_in,
                              void* d_out, int out_size)
{
    const float* outputs = (const float*)d_in[0];
    const void*  tests   = d_in[1];
    const float* W1      = (const float*)d_in[2];
    const float* b1      = (const float*)d_in[3];
    const float* W2      = (const float*)d_in[4];
    float*       out     = (float*)d_out;

    int B = in_sizes[0] / ROWF;   // 8192

    int sm = 0;
    cudaDeviceGetAttribute(&sm, cudaDevAttrMultiProcessorCount, 0);
    if (sm <= 0) sm = 148;

    iin_kernel<<<2 * sm, THREADS>>>(
        outputs, (const int*)tests, (const long long*)tests, W1, b1, W2, out, B);
}

// round 6
// speedup vs baseline: 1.7662x; 1.7662x over previous
#include <cuda_runtime.h>

#define HID 10
#define ROWF 2048                 // floats per row
#define PAIRS 12
#define WARPS (PAIRS * 2)
#define THREADS (WARPS * 32)

// dynamic smem layout (floats)
#define ROWAREA   (WARPS * 2048)       // per warp: 2 buffers x 1024 floats (4KB each)
#define AQ_OFF    ROWAREA              // 160 ull = 320 floats
#define BQ_OFF    (AQ_OFF + 320)       // 176 ull = 352 floats
#define EPI_OFF   (BQ_OFF + 352)       // 20 floats
#define PAIR_OFF  (EPI_OFF + 20)       // 12 pairs x 2 parity x 2 halves x float4 = 192 floats
#define SMEM_FLOATS (PAIR_OFF + 192)
#define SMEM_BYTES  (SMEM_FLOATS * 4)

typedef unsigned long long ull;

__device__ __forceinline__ void fma2(ull& acc, ull a, ull b) {
    asm("fma.rn.f32x2 %0, %1, %2, %0;" : "+l"(acc) : "l"(a), "l"(b));
}
__device__ __forceinline__ float2 unp(ull v) {
    float2 r; asm("mov.b64 {%0,%1}, %2;" : "=f"(r.x), "=f"(r.y) : "l"(v)); return r;
}
__device__ __forceinline__ ull pk(float lo, float hi) {
    ull v; asm("mov.b64 %0, {%1,%2};" : "=l"(v) : "f"(lo), "f"(hi)); return v;
}
__device__ __forceinline__ void cpa16(unsigned dst, const void* src) {
    asm volatile("cp.async.cg.shared.global [%0], [%1], 16;" :: "r"(dst), "l"(src));
}

__global__ __launch_bounds__(THREADS, 1)
void iin_kernel(const float* __restrict__ outputs,
                const int* __restrict__ tests32,
                const long long* __restrict__ tests64,
                const float* __restrict__ W1,
                const float* __restrict__ b1,
                const float* __restrict__ W2,
                float* __restrict__ out,
                int B)
{
    extern __shared__ float smem[];
    ull*    aQ   = (ull*)(smem + AQ_OFF);   // [t2*20 + sub*10 + j] : f32x2(W1[32+4t2+2sub][j], W1[33+..][j])
    ull*    bQ   = (ull*)(smem + BQ_OFF);   // [q*22  + sub*10 + j] : person-half, stride 22
    float*  epi  = smem + EPI_OFF;          // w2[0..9], b1[10..19]
    float4* pslt = (float4*)(smem + PAIR_OFF);

    const int tid  = threadIdx.x;
    const int lane = tid & 31;
    const int warp = tid >> 5;
    const int pair = warp >> 1;
    const int half = warp & 1;              // 0: wires 0-31, 1: wires 32-63

    for (int idx = tid; idx < 160; idx += THREADS) {
        int t2 = idx / 20, r = idx % 20, sub = r / 10, j = r % 10;
        int d0 = 32 + 4 * t2 + 2 * sub;
        aQ[t2 * 20 + sub * 10 + j] = pk(W1[d0 * HID + j], W1[(d0 + 1) * HID + j]);
        int e0 = 4 * t2 + 2 * sub;
        bQ[t2 * 22 + sub * 10 + j] = pk(W1[e0 * HID + j], W1[(e0 + 1) * HID + j]);
    }
    if (tid < 10) { epi[tid] = W2[tid]; epi[tid + 10] = b1[tid]; }
    __syncthreads();

    // tests dtype probe: int64 -> every odd int32 word is a zero high-half
    int pidx = 2 * lane + 1; if (pidx > 2 * B - 1) pidx = 2 * B - 1;
    const bool idx32 = __any_sync(0xffffffffu, tests32[pidx] != 0);

    // per-warp double buffers (4KB each)
    float* buf0 = smem + warp * 2048;
    unsigned sbase;
    asm("{ .reg .u64 t; cvta.to.shared.u64 t, %1; cvt.u32.u64 %0, t; }"
        : "=r"(sbase) : "l"(buf0));
    unsigned sb[2] = { sbase, sbase + 4096u };
    const float* bufp[2] = { buf0, buf0 + 1024 };

    // lane copies chunks c = lane + 32u, u=0..7 (256 chunks = 4KB half-row), XOR-swizzled
    unsigned dsto[8];
#pragma unroll
    for (int u = 0; u < 8; ++u) {
        unsigned c = lane + 32u * u, w = c >> 3, k = c & 7;
        dsto[u] = (8u * w + (k ^ (w & 7u))) * 16u;
    }
    const size_t srcoff = (size_t)half * 4096u + (size_t)lane * 16u;

    const unsigned q = lane & 7;
    const double2* bp2 = (const double2*)(bQ + q * 22);
    const int barid = pair + 1;

    const int gp      = blockIdx.x * PAIRS + pair;
    const int gstride = gridDim.x * PAIRS;

    int cur = 0;
    if (gp < B) {
        const char* src = (const char*)(outputs + (size_t)gp * ROWF) + srcoff;
#pragma unroll
        for (int u = 0; u < 8; ++u) cpa16(sb[0] + dsto[u], src + 512u * u);
        asm volatile("cp.async.commit_group;");
    }

    int parity = 0;
    for (int row = gp; row < B; row += gstride, parity ^= 1) {
        // person / location (independent of buffers)
        int person, loc;
        if (idx32) { person = tests32[2 * row];      loc = tests32[2 * row + 1]; }
        else       { person = (int)tests64[2 * row]; loc = (int)tests64[2 * row + 1]; }
        const float4* grow = (const float4*)outputs + (size_t)row * 512;
        float4 pv = grow[(unsigned)person * 8 + q];      // one 128B line, coalesced by 8 lanes

        // prefetch next row's half
        int nxt = row + gstride;
        if (nxt < B) {
            const char* src = (const char*)(outputs + (size_t)nxt * ROWF) + srcoff;
#pragma unroll
            for (int u = 0; u < 8; ++u) cpa16(sb[cur ^ 1] + dsto[u], src + 512u * u);
            asm volatile("cp.async.commit_group;");
            asm volatile("cp.async.wait_group 1;");
        } else {
            asm volatile("cp.async.wait_group 0;");
        }
        __syncwarp();

        const double2* rp = (const double2*)bufp[cur];

        // ---- main loop: 1 wire/lane (local wire = lane) ----
        ull acc[HID];
#pragma unroll
        for (int j = 0; j < HID; ++j) acc[j] = 0ULL;
#pragma unroll
        for (int t2 = 0; t2 < 8; ++t2) {
            double2 x = rp[8u * (unsigned)lane + ((unsigned)t2 ^ ((unsigned)lane & 7u))];
            ull x01 = __double_as_longlong(x.x), x23 = __double_as_longlong(x.y);
            const double2* ap = (const double2*)(aQ + t2 * 20);
#pragma unroll
            for (int jj = 0; jj < 5; ++jj) {
                double2 A0 = ap[jj], A1 = ap[jj + 5];
                fma2(acc[2 * jj],     x01, __double_as_longlong(A0.x));
                fma2(acc[2 * jj + 1], x01, __double_as_longlong(A0.y));
                fma2(acc[2 * jj],     x23, __double_as_longlong(A1.x));
                fma2(acc[2 * jj + 1], x23, __double_as_longlong(A1.y));
            }
        }

        // ---- person partial: 8-lane groups, member q handles d = 4q..4q+3 ----
        ull xp01 = pk(pv.x, pv.y), xp23 = pk(pv.z, pv.w);
        ull s2[HID];
#pragma unroll
        for (int j = 0; j < HID; ++j) s2[j] = 0ULL;
#pragma unroll
        for (int jj = 0; jj < 5; ++jj) {
            double2 B0 = bp2[jj], B1 = bp2[jj + 5];
            fma2(s2[2 * jj],     xp01, __double_as_longlong(B0.x));
            fma2(s2[2 * jj + 1], xp01, __double_as_longlong(B0.y));
            fma2(s2[2 * jj],     xp23, __double_as_longlong(B1.x));
            fma2(s2[2 * jj + 1], xp23, __double_as_longlong(B1.y));
        }
        float pb[HID];
#pragma unroll
        for (int j = 0; j < HID; ++j) { float2 f = unp(s2[j]); pb[j] = f.x + f.y; }
#pragma unroll
        for (int off = 4; off; off >>= 1)
#pragma unroll
            for (int j = 0; j < HID; ++j)
                pb[j] += __shfl_xor_sync(0xffffffffu, pb[j], off);

        // ---- logit (1 per lane); b2 cancels in lse - logit ----
        float lg = 0.f;
#pragma unroll
        for (int j = 0; j < HID; ++j) {
            float2 f = unp(acc[j]);
            float h = fmaxf(f.x + f.y + pb[j] + epi[10 + j], 0.f);
            lg = fmaf(h, epi[j], lg);
        }

        // ---- warp-local softmax stats over 32 wires ----
        float m = lg;
#pragma unroll
        for (int off = 16; off; off >>= 1)
            m = fmaxf(m, __shfl_xor_sync(0xffffffffu, m, off));
        float s = __expf(lg - m);
#pragma unroll
        for (int off = 16; off; off >>= 1)
            s += __shfl_xor_sync(0xffffffffu, s, off);
        float sel = __shfl_sync(0xffffffffu, lg, loc & 31);   // valid iff (loc>>5)==half

        // ---- pair combine via smem slot + named barrier ----
        float4* slot = pslt + ((pair * 2 + parity) * 2);
        if (lane == 0) slot[half] = make_float4(m, s, sel, 0.f);
        asm volatile("bar.sync %0, %1;" :: "r"(barid), "r"(64) : "memory");

        if (half == 0 && lane == 0) {
            float4 o = slot[1];
            float M  = fmaxf(m, o.x);
            float S  = s * __expf(m - M) + o.y * __expf(o.x - M);
            float lv = (loc >> 5) ? o.z : sel;
            out[row] = M + __logf(S) - lv;
        }
        cur ^= 1;
    }
}

extern "C" void kernel_launch(void* const* d_in, const int* in_sizes, int n_in,
                              void* d_out, int out_size)
{
    const float* outputs = (const float*)d_in[0];
    const void*  tests   = d_in[1];
    const float* W1      = (const float*)d_in[2];
    const float* b1      = (const float*)d_in[3];
    const float* W2      = (const float*)d_in[4];
    float*       out     = (float*)d_out;

    int B = in_sizes[0] / ROWF;   // 8192

    int sm = 0;
    cudaDeviceGetAttribute(&sm, cudaDevAttrMultiProcessorCount, 0);
    if (sm <= 0) sm = 148;
    cudaFuncSetAttribute(iin_kernel, cudaFuncAttributeMaxDynamicSharedMemorySize, SMEM_BYTES);

    iin_kernel<<<sm, THREADS, SMEM_BYTES>>>(
        outputs, (const int*)tests, (const long long*)tests, W1, b1, W2, out, B);
}

// round 7
// speedup vs baseline: 2.4484x; 1.3863x over previous
#include <cuda_runtime.h>

#define HID 10
#define ROWF 2048                 // floats per row
#define WARPS 20
#define THREADS (WARPS * 32)

// dynamic smem (floats): per-warp single 8KB row buffer + weight tables
#define ROWAREA   (WARPS * 2048)
#define AQ_OFF    ROWAREA              // 160 ull = 320 floats
#define BQ_OFF    (AQ_OFF + 320)       // 176 ull = 352 floats
#define EPI_OFF   (BQ_OFF + 352)       // 20 floats
#define SMEM_FLOATS (EPI_OFF + 20)
#define SMEM_BYTES  (SMEM_FLOATS * 4)

typedef unsigned long long ull;

__device__ __forceinline__ void fma2(ull& acc, ull a, ull b) {
    asm("fma.rn.f32x2 %0, %1, %2, %0;" : "+l"(acc) : "l"(a), "l"(b));
}
__device__ __forceinline__ float2 unp(ull v) {
    float2 r; asm("mov.b64 {%0,%1}, %2;" : "=f"(r.x), "=f"(r.y) : "l"(v)); return r;
}
__device__ __forceinline__ ull pk(float lo, float hi) {
    ull v; asm("mov.b64 %0, {%1,%2};" : "=l"(v) : "f"(lo), "f"(hi)); return v;
}
__device__ __forceinline__ void cpa16(unsigned dst, const void* src) {
    asm volatile("cp.async.cg.shared.global [%0], [%1], 16;" :: "r"(dst), "l"(src));
}

// issue a full-row (8KB) coalesced cp.async load into the warp's swizzled buffer
__device__ __forceinline__ void load_row(unsigned sbase, const float* outputs,
                                         int row, unsigned lane) {
    const char* src = (const char*)(outputs + (size_t)row * ROWF) + (size_t)lane * 16u;
#pragma unroll
    for (int u = 0; u < 16; ++u) {
        unsigned c = lane + 32u * (unsigned)u, w = c >> 3, k = c & 7u;
        cpa16(sbase + (8u * w + (k ^ (w & 7u))) * 16u, src + 512u * u);
    }
    asm volatile("cp.async.commit_group;");
}

__global__ __launch_bounds__(THREADS, 1)
void iin_kernel(const float* __restrict__ outputs,
                const int* __restrict__ tests32,
                const long long* __restrict__ tests64,
                const float* __restrict__ W1,
                const float* __restrict__ b1,
                const float* __restrict__ W2,
                float* __restrict__ out,
                int B)
{
    extern __shared__ float smem[];
    ull*   aQ  = (ull*)(smem + AQ_OFF);   // [t2*20 + sub*10 + j] : f32x2(W1[32+4t2+2sub][j], W1[33+..][j])
    ull*   bQ  = (ull*)(smem + BQ_OFF);   // [q*22  + sub*10 + j] : person-half, stride 22 (conflict-free)
    float* epi = smem + EPI_OFF;          // w2[0..9], b1[10..19]

    const int tid  = threadIdx.x;
    const unsigned lane = tid & 31;
    const int warp = tid >> 5;

    for (int idx = tid; idx < 160; idx += THREADS) {
        int t2 = idx / 20, r = idx % 20, sub = r / 10, j = r % 10;
        int d0 = 32 + 4 * t2 + 2 * sub;
        aQ[t2 * 20 + sub * 10 + j] = pk(W1[d0 * HID + j], W1[(d0 + 1) * HID + j]);
        int e0 = 4 * t2 + 2 * sub;
        bQ[t2 * 22 + sub * 10 + j] = pk(W1[e0 * HID + j], W1[(e0 + 1) * HID + j]);
    }
    if (tid < 10) { epi[tid] = W2[tid]; epi[tid + 10] = b1[tid]; }
    __syncthreads();

    // tests dtype probe: int64 -> every odd int32 word is a zero high-half
    int pidx = 2 * (int)lane + 1; if (pidx > 2 * B - 1) pidx = 2 * B - 1;
    const bool idx32 = __any_sync(0xffffffffu, tests32[pidx] != 0);

    float* buf = smem + warp * 2048;
    unsigned sbase;
    asm("{ .reg .u64 t; cvta.to.shared.u64 t, %1; cvt.u32.u64 %0, t; }"
        : "=r"(sbase) : "l"(buf));
    const double2* rp = (const double2*)buf;

    const unsigned q = lane & 7u;
    const double2* bp2 = (const double2*)(bQ + q * 22);

    const int gw      = blockIdx.x * WARPS + warp;
    const int gstride = gridDim.x * WARPS;

    if (gw < B) load_row(sbase, outputs, gw, lane);

    for (int row = gw; row < B; row += gstride) {
        int person, loc;
        if (idx32) { person = tests32[2 * row];      loc = tests32[2 * row + 1]; }
        else       { person = (int)tests64[2 * row]; loc = (int)tests64[2 * row + 1]; }

        asm volatile("cp.async.wait_group 0;");
        __syncwarp();

        // ---- person partial first (frees s2 before the main loop) ----
        // 8-lane groups: member q handles d = 4q..4q+3; person vec chunk q (broadcast x4 groups)
        double2 pvc = rp[8u * (unsigned)person + (q ^ ((unsigned)person & 7u))];
        ull xp01 = __double_as_longlong(pvc.x), xp23 = __double_as_longlong(pvc.y);
        ull s2[HID];
#pragma unroll
        for (int j = 0; j < HID; ++j) s2[j] = 0ULL;
#pragma unroll
        for (int jj = 0; jj < 5; ++jj) {
            double2 B0 = bp2[jj], B1 = bp2[jj + 5];
            fma2(s2[2 * jj],     xp01, __double_as_longlong(B0.x));
            fma2(s2[2 * jj + 1], xp01, __double_as_longlong(B0.y));
            fma2(s2[2 * jj],     xp23, __double_as_longlong(B1.x));
            fma2(s2[2 * jj + 1], xp23, __double_as_longlong(B1.y));
        }
        float pb[HID];
#pragma unroll
        for (int j = 0; j < HID; ++j) { float2 f = unp(s2[j]); pb[j] = f.x + f.y; }
#pragma unroll
        for (int off = 4; off; off >>= 1)
#pragma unroll
            for (int j = 0; j < HID; ++j)
                pb[j] += __shfl_xor_sync(0xffffffffu, pb[j], off);
#pragma unroll
        for (int j = 0; j < HID; ++j) pb[j] += epi[10 + j];

        // ---- main loop: 2 wires/lane (w0=lane, w1=lane+32), weights shared across both ----
        ull a0[HID], a1[HID];
#pragma unroll
        for (int j = 0; j < HID; ++j) { a0[j] = 0ULL; a1[j] = 0ULL; }
#pragma unroll
        for (int t2 = 0; t2 < 8; ++t2) {
            double2 xa = rp[8u * lane        + ((unsigned)t2 ^ (lane & 7u))];
            double2 xb = rp[8u * (lane + 32) + ((unsigned)t2 ^ (lane & 7u))];
            ull xa01 = __double_as_longlong(xa.x), xa23 = __double_as_longlong(xa.y);
            ull xb01 = __double_as_longlong(xb.x), xb23 = __double_as_longlong(xb.y);
            const double2* ap = (const double2*)(aQ + t2 * 20);
#pragma unroll
            for (int jj = 0; jj < 5; ++jj) {
                double2 A0 = ap[jj], A1 = ap[jj + 5];
                ull A0x = __double_as_longlong(A0.x), A0y = __double_as_longlong(A0.y);
                ull A1x = __double_as_longlong(A1.x), A1y = __double_as_longlong(A1.y);
                fma2(a0[2 * jj],     xa01, A0x); fma2(a0[2 * jj + 1], xa01, A0y);
                fma2(a0[2 * jj],     xa23, A1x); fma2(a0[2 * jj + 1], xa23, A1y);
                fma2(a1[2 * jj],     xb01, A0x); fma2(a1[2 * jj + 1], xb01, A0y);
                fma2(a1[2 * jj],     xb23, A1x); fma2(a1[2 * jj + 1], xb23, A1y);
            }
        }

        // all buffer reads are consumed above; safe to refill the single buffer
        __syncwarp();
        int nxt = row + gstride;
        if (nxt < B) load_row(sbase, outputs, nxt, lane);

        // ---- logits (b2 cancels in lse - logit) ----
        float lg0 = 0.f, lg1 = 0.f;
#pragma unroll
        for (int j = 0; j < HID; ++j) {
            float2 f0 = unp(a0[j]), f1 = unp(a1[j]);
            float q0 = fmaxf(f0.x + f0.y + pb[j], 0.f);
            float q1 = fmaxf(f1.x + f1.y + pb[j], 0.f);
            lg0 = fmaf(q0, epi[j], lg0);
            lg1 = fmaf(q1, epi[j], lg1);
        }

        // ---- log-softmax over 64 wires (full-warp butterfly) ----
        float m = fmaxf(lg0, lg1);
#pragma unroll
        for (int off = 16; off; off >>= 1)
            m = fmaxf(m, __shfl_xor_sync(0xffffffffu, m, off));
        float s = __expf(lg0 - m) + __expf(lg1 - m);
#pragma unroll
        for (int off = 16; off; off >>= 1)
            s += __shfl_xor_sync(0xffffffffu, s, off);
        float lse = m + __logf(s);

        float sel = (loc >= 32) ? lg1 : lg0;
        float lv  = __shfl_sync(0xffffffffu, sel, loc & 31);
        if (lane == 0) out[row] = lse - lv;
    }
}

extern "C" void kernel_launch(void* const* d_in, const int* in_sizes, int n_in,
                              void* d_out, int out_size)
{
    const float* outputs = (const float*)d_in[0];
    const void*  tests   = d_in[1];
    const float* W1      = (const float*)d_in[2];
    const float* b1      = (const float*)d_in[3];
    const float* W2      = (const float*)d_in[4];
    float*       out     = (float*)d_out;

    int B = in_sizes[0] / ROWF;   // 8192

    int sm = 0;
    cudaDeviceGetAttribute(&sm, cudaDevAttrMultiProcessorCount, 0);
    if (sm <= 0) sm = 148;
    cudaFuncSetAttribute(iin_kernel, cudaFuncAttributeMaxDynamicSharedMemorySize, SMEM_BYTES);

    iin_kernel<<<sm, THREADS, SMEM_BYTES>>>(
        outputs, (const int*)tests, (const long long*)tests, W1, b1, W2, out, B);
}